// round 10
// baseline (speedup 1.0000x reference)
#include <cuda_runtime.h>

#define POOL   7
#define NPIX   49
#define BATCH  2
#define NBOX   1000
#define CCH    256
#define C4     (CCH / 4)
#define ITEMS  (NPIX * C4)      // 3136 float4 items per box

// ---------------------------------------------------------------------------
// Fused kernel: one block per (box, channel-half). 4000 blocks x 256 threads.
//  - finer blocks halve wave-quantization tail waste (8 blocks/SM, 100% occ)
//  - slot (stable-sort rank) computed in-block by predicate count.
//  - 49 threads precompute per-pixel corner indices + weights into shared.
//  - 6 unconditional iterations + warp-0 tail (pixel 48).
//  - __stcs output stores: evict-first, keep L2 for feature-map reads.
// ---------------------------------------------------------------------------
__global__ __launch_bounds__(256, 8) void roi_kernel(
    const float* __restrict__ boxes,
    const float* __restrict__ fm0,
    const float* __restrict__ fm1,
    const float* __restrict__ fm2,
    const float* __restrict__ fm3,
    const int*   __restrict__ level,
    float*       __restrict__ out)
{
    __shared__ int4   sIdx[NPIX];   // corner base indices (float4 units)
    __shared__ float4 sW[NPIX];     // {wy, wx, validf, -}
    __shared__ int    sRed[8];
    __shared__ int    sSlot;

    const int blk  = blockIdx.x;             // 0..3999
    const int box  = blk >> 1;                // 0..1999
    const int half = blk & 1;                 // channel half
    const int b    = (box >= NBOX) ? 1 : 0;
    const int ii   = box - b * NBOX;          // index within batch
    const int tid  = threadIdx.x;
    const int warp = tid >> 5, lane = tid & 31;

    const int myLv = __ldg(level + box);     // 1..4

    const float* fm; int S;
    switch (myLv - 1) {
        case 0:  fm = fm0; S = 256; break;
        case 1:  fm = fm1; S = 128; break;
        case 2:  fm = fm2; S = 64;  break;
        default: fm = fm3; S = 32;  break;
    }

    // ---- slot: predicate count over this batch's 1000 levels ----
    {
        const int* lvArr = level + b * NBOX;
        int cnt = 0;
        #pragma unroll
        for (int j = tid; j < NBOX; j += 256) {
            const int lj = __ldg(lvArr + j);
            cnt += (lj < myLv) || (lj == myLv && j < ii);
        }
        #pragma unroll
        for (int d = 16; d; d >>= 1) cnt += __shfl_xor_sync(0xffffffffu, cnt, d);
        if (lane == 0) sRed[warp] = cnt;
    }

    // ---- per-pixel params (threads 0..48) ----
    if (tid < NPIX) {
        const int py = tid / POOL;
        const int px = tid - py * POOL;
        const float sm1 = (float)(S - 1);

        const float y1 = __ldg(boxes + box * 4 + 0);
        const float x1 = __ldg(boxes + box * 4 + 1);
        const float y2 = __ldg(boxes + box * 4 + 2);
        const float x2 = __ldg(boxes + box * 4 + 3);

        const float in_y = y1 * sm1 + (float)py * ((y2 - y1) * sm1 / 6.0f);
        const float in_x = x1 * sm1 + (float)px * ((x2 - x1) * sm1 / 6.0f);

        const bool valid = (in_y >= 0.0f) && (in_y <= sm1) &&
                           (in_x >= 0.0f) && (in_x <= sm1);

        const float fy = floorf(in_y);
        const float fx = floorf(in_x);
        const int ty = (int)fminf(fmaxf(fy, 0.0f), sm1);
        const int by = min(ty + 1, S - 1);
        const int lx = (int)fminf(fmaxf(fx, 0.0f), sm1);
        const int rx = min(lx + 1, S - 1);

        const int rowT = (b * S + ty) * S;
        const int rowB = (b * S + by) * S;
        sIdx[tid] = make_int4((rowT + lx) * C4, (rowT + rx) * C4,
                              (rowB + lx) * C4, (rowB + rx) * C4);
        sW[tid] = make_float4(in_y - fy, in_x - fx, valid ? 1.0f : 0.0f, 0.0f);
    }
    __syncthreads();
    if (tid == 0) {
        int s = 0;
        #pragma unroll
        for (int w = 0; w < 8; ++w) s += sRed[w];
        sSlot = s;
    }
    __syncthreads();

    const float4* f4 = (const float4*)fm;
    float4* o4 = (float4*)out + (size_t)(b * NBOX + sSlot) * ITEMS;

    const int c    = (tid & 31) + (half << 5);  // channel group 0..63
    const int slot = tid >> 5;                  // 0..7 (== warp id)

    #pragma unroll
    for (int k = 0; k < 6; ++k) {
        const int pix = k * 8 + slot;           // 0..47

        const int4   id = sIdx[pix];
        const float4 w  = sW[pix];              // w.x=wy, w.y=wx, w.z=valid

        const float4 tl = __ldg(f4 + id.x + c);
        const float4 tr = __ldg(f4 + id.y + c);
        const float4 bl = __ldg(f4 + id.z + c);
        const float4 br = __ldg(f4 + id.w + c);

        float4 r;
        {
            float top, bot;
            top = tl.x + (tr.x - tl.x) * w.y; bot = bl.x + (br.x - bl.x) * w.y;
            r.x = (top + (bot - top) * w.x) * w.z;
            top = tl.y + (tr.y - tl.y) * w.y; bot = bl.y + (br.y - bl.y) * w.y;
            r.y = (top + (bot - top) * w.x) * w.z;
            top = tl.z + (tr.z - tl.z) * w.y; bot = bl.z + (br.z - bl.z) * w.y;
            r.z = (top + (bot - top) * w.x) * w.z;
            top = tl.w + (tr.w - tl.w) * w.y; bot = bl.w + (br.w - bl.w) * w.y;
            r.w = (top + (bot - top) * w.x) * w.z;
        }
        __stcs(o4 + pix * C4 + c, r);
    }

    // tail: pixel 48 (warp 0 only)
    if (slot == 0) {
        const int4   id = sIdx[48];
        const float4 w  = sW[48];
        const float4 tl = __ldg(f4 + id.x + c);
        const float4 tr = __ldg(f4 + id.y + c);
        const float4 bl = __ldg(f4 + id.z + c);
        const float4 br = __ldg(f4 + id.w + c);
        float4 r;
        float top, bot;
        top = tl.x + (tr.x - tl.x) * w.y; bot = bl.x + (br.x - bl.x) * w.y;
        r.x = (top + (bot - top) * w.x) * w.z;
        top = tl.y + (tr.y - tl.y) * w.y; bot = bl.y + (br.y - bl.y) * w.y;
        r.y = (top + (bot - top) * w.x) * w.z;
        top = tl.z + (tr.z - tl.z) * w.y; bot = bl.z + (br.z - bl.z) * w.y;
        r.z = (top + (bot - top) * w.x) * w.z;
        top = tl.w + (tr.w - tl.w) * w.y; bot = bl.w + (br.w - bl.w) * w.y;
        r.w = (top + (bot - top) * w.x) * w.z;
        __stcs(o4 + 48 * C4 + c, r);
    }
}

// ---------------------------------------------------------------------------
// Launch: single fused kernel.
// ---------------------------------------------------------------------------
extern "C" void kernel_launch(void* const* d_in, const int* in_sizes, int n_in,
                              void* d_out, int out_size) {
    const float* boxes = (const float*)d_in[0];
    const float* fm0   = (const float*)d_in[1];
    const float* fm1   = (const float*)d_in[2];
    const float* fm2   = (const float*)d_in[3];
    const float* fm3   = (const float*)d_in[4];
    const int*   level = (const int*)  d_in[5];
    float*       out   = (float*)d_out;

    roi_kernel<<<BATCH * NBOX * 2, 256>>>(boxes, fm0, fm1, fm2, fm3, level, out);
}